// round 16
// baseline (speedup 1.0000x reference)
#include <cuda_runtime.h>
#include <cuda_fp16.h>
#include <cstdint>
#include <cstddef>

#define NEDGES 500000
#define NNODES 200000

constexpr int MROWS   = 500096;            // mult of 128
constexpr int NROWS   = 200064;            // nodes padded to mult of 64
constexpr int TILES64 = MROWS / 64;        // 7814 edge-row tiles
constexpr int TILESN  = NROWS / 64;        // 3126 node-row tiles
constexpr int TILESH  = MROWS / 128;       // 3907

// ---------------- device scratch ----------------
__device__ __half g_hp[(size_t)NROWS * 128];        // h fp16, k-permuted (pad rows zero)
__device__ __half g_X1[(size_t)MROWS * 512];        // activations fp16, k-permuted
__device__ __half g_X2[(size_t)MROWS * 512];        // also hosts UV [NROWS][1024]
__device__ __half g_W0m[4 * 1024 * 32];             // merged W0 [kc][n(U|V)][kp]
__device__ __half g_Whh[2 * 16 * 512 * 32];         // hidden W [l][kc][n][kp]
__device__ __half g_WHh[16 * 32 * 32];              // head W [kc][n][kp]
__device__ float  g_sc[3 * 512];
__device__ float  g_sh[3 * 512];
__device__ float  g_scp[512];                       // layer-0 BN scale, permuted
__device__ float  g_shp[512];                       // layer-0 BN shift, permuted
__device__ float  g_hb[32];

// k-permutation within a 32-k chunk: lane tig gets its 8 fragment halves contiguous.
__host__ __device__ __forceinline__ int kperm(int k) {
    return ((k & 7) >> 1) * 8 + ((k >> 4) & 1) * 4 + ((k >> 3) & 1) * 2 + (k & 1);
}

// ---------------- helpers ----------------
__device__ __forceinline__ void cp16s(uint32_t s, const void* g) {
    asm volatile("cp.async.cg.shared.global [%0], [%1], 16;\n" :: "r"(s), "l"(g));
}
__device__ __forceinline__ void cp16(void* s, const void* g) {
    unsigned ss = (unsigned)__cvta_generic_to_shared(s);
    asm volatile("cp.async.cg.shared.global [%0], [%1], 16;\n" :: "r"(ss), "l"(g));
}
__device__ __forceinline__ void cp_commit() { asm volatile("cp.async.commit_group;\n"); }
template<int N> __device__ __forceinline__ void cp_wait() {
    asm volatile("cp.async.wait_group %0;\n" :: "n"(N) : "memory");
}
__device__ __forceinline__ void mma16(float* c,
                                      unsigned a0, unsigned a1, unsigned a2, unsigned a3,
                                      unsigned b0, unsigned b1) {
    asm volatile(
        "mma.sync.aligned.m16n8k16.row.col.f32.f16.f16.f32 "
        "{%0,%1,%2,%3},{%4,%5,%6,%7},{%8,%9},{%0,%1,%2,%3};"
        : "+f"(c[0]), "+f"(c[1]), "+f"(c[2]), "+f"(c[3])
        : "r"(a0), "r"(a1), "r"(a2), "r"(a3), "r"(b0), "r"(b1));
}
// fast ELU: __expf = MUFU.EX2 path, abs err ~1e-6
__device__ __forceinline__ float eluf(float v) { return v > 0.f ? v : (__expf(v) - 1.f); }

// ---------------- prep: convert everything to permuted fp16, fold BN ----------------
__global__ void prep_kernel(
    const float* __restrict__ h,
    const float* __restrict__ W0,  const float* __restrict__ b0,
    const float* __restrict__ Wh,  const float* __restrict__ bh,
    const float* __restrict__ gm,  const float* __restrict__ bt,
    const float* __restrict__ mn,  const float* __restrict__ vr,
    const float* __restrict__ Wpi, const float* __restrict__ bpi,
    const float* __restrict__ Wsg, const float* __restrict__ bsg,
    const float* __restrict__ Wmu, const float* __restrict__ bmu)
{
    int st = gridDim.x * blockDim.x;
    int t0 = blockIdx.x * blockDim.x + threadIdx.x;
    for (int o = t0; o < NNODES * 128; o += st) {
        int node = o >> 7, kk = o & 127;
        int ch = kk >> 5, k = kk & 31;
        g_hp[(size_t)node * 128 + ch * 32 + kperm(k)] = __float2half(h[o]);
    }
    for (int o = t0; o < 4 * 1024 * 32; o += st) {
        int kc = o >> 15, n = (o >> 5) & 1023, k = o & 31;
        float v = (n < 512) ? W0[(size_t)(kc * 32 + k) * 512 + n]
                            : W0[(size_t)(kc * 32 + k + 128) * 512 + (n - 512)];
        g_W0m[(size_t)kc * 32768 + n * 32 + kperm(k)] = __float2half(v);
    }
    for (int o = t0; o < 2 * 16 * 512 * 32; o += st) {
        int l = o >> 18;
        int kc = (o >> 14) & 15, n = (o >> 5) & 511, k = o & 31;
        g_Whh[(size_t)l * 262144 + (size_t)kc * 16384 + n * 32 + kperm(k)] =
            __float2half(Wh[(size_t)l * 262144 + (size_t)(kc * 32 + k) * 512 + n]);
    }
    for (int o = t0; o < 16 * 32 * 32; o += st) {
        int kc = o >> 10, n = (o >> 5) & 31, k = o & 31;
        int kk = kc * 32 + k;
        float v = (n < 10) ? Wpi[kk * 10 + n]
                : (n < 20) ? Wsg[kk * 10 + (n - 10)]
                : (n < 30) ? Wmu[kk * 10 + (n - 20)] : 0.f;
        g_WHh[kc * 1024 + n * 32 + kperm(k)] = __float2half(v);
    }
    for (int i = t0; i < 3 * 512; i += st) {
        int l = i >> 9, c = i & 511;
        float s = gm[i] * rsqrtf(vr[i] + 1e-5f);
        float bb = (l == 0) ? b0[c] : bh[(l - 1) * 512 + c];
        g_sc[i] = s;
        g_sh[i] = (bb - mn[i]) * s + bt[i];
        if (l == 0) {
            int pi = (c & ~31) + kperm(c & 31);
            g_scp[pi] = s;
            g_shp[pi] = (bb - mn[i]) * s + bt[i];
        }
    }
    for (int i = t0; i < 32; i += st)
        g_hb[i] = (i < 10) ? bpi[i] : (i < 20) ? bsg[i - 10] : (i < 30) ? bmu[i - 20] : 0.f;
}

// ---------------- hidden GEMM (R14 config: fp16, warp 32x64, fully unrolled) ----------------
// CTA tile M=64 x N=128, 128 threads (4 warps in 2x2), 4 CTAs/SM.
// K chunk 32, 4-stage ring, prefetch distance 3, 1 barrier/chunk.
constexpr int SMEM_MAIN_B = 16384 + 32768;   // 49,152 (x4 CTAs = 196,608)

template<int KDIM, int NW, bool ACT>
__global__ void __launch_bounds__(128, 4)
gemm_kernel(const __half* __restrict__ Ag,    // [rows][KDIM] fp16 permuted
            const __half* __restrict__ W,     // [KDIM/32][NW][32] fp16 permuted
            const float*  __restrict__ sc,
            const float*  __restrict__ sh,
            __half* __restrict__ outp)        // [rows][NW] fp16 permuted
{
    extern __shared__ char sm[];
    char* As = sm;                     // 4 * 4096 B
    char* Bs = sm + 16384;             // 4 * 8192 B

    const int tid  = threadIdx.x;
    const int tile = blockIdx.y;
    const int n0   = blockIdx.x * 128;
    constexpr int NC = KDIM / 32;

    const int seg = tid & 3;               // 16B segment in 64B row
    const int r0  = tid >> 2;              // 0..31
    const uint32_t sAb = (uint32_t)__cvta_generic_to_shared(As);
    const uint32_t sBb = (uint32_t)__cvta_generic_to_shared(Bs);
    const uint32_t dA0 = sAb + (uint32_t)(r0 * 64 + seg * 16);
    const uint32_t dB0 = sBb + (uint32_t)(r0 * 64 + seg * 16);
    const char* AgB = (const char*)Ag;
    const char* WB  = (const char*)W;
    const char* srcA0 = AgB + (size_t)(tile * 64 + r0) * (KDIM * 2) + seg * 16;
    const char* srcB0 = WB + (size_t)(n0 + r0) * 64 + seg * 16;

    auto prefetch = [&](int kc) {
        const int stg = kc & 3;
        const uint32_t soA = (uint32_t)stg * 4096;
        const uint32_t soB = (uint32_t)stg * 8192;
        const char* s = srcA0 + kc * 64;
        #pragma unroll
        for (int it = 0; it < 2; it++)
            cp16s(dA0 + soA + it * 2048, s + (size_t)it * 32 * (KDIM * 2));
        const char* sb = srcB0 + (size_t)kc * (NW * 64);
        #pragma unroll
        for (int it = 0; it < 4; it++)
            cp16s(dB0 + soB + it * 2048, sb + (size_t)it * 2048);
        cp_commit();
    };

    const int wid = tid >> 5, lane = tid & 31;
    const int wm = wid >> 1, wn = wid & 1;            // 2x2 warp grid
    const int g = lane >> 2, tig = lane & 3;
    const int aoff = (wm * 32 + g) * 64 + tig * 16;
    const int boff = (wn * 64 + g) * 64 + tig * 16;

    float c[2][8][4];
    #pragma unroll
    for (int i = 0; i < 2; i++)
        #pragma unroll
        for (int j = 0; j < 8; j++)
            #pragma unroll
            for (int q = 0; q < 4; q++) c[i][j][q] = 0.f;

    prefetch(0);
    prefetch(1);
    prefetch(2);

    #pragma unroll
    for (int kc = 0; kc < NC; kc++) {
        if (kc + 3 < NC) cp_wait<2>();
        else if (kc + 2 < NC) cp_wait<1>();
        else cp_wait<0>();
        __syncthreads();
        if (kc + 3 < NC) prefetch(kc + 3);

        const int stg = kc & 3;
        const char* Ab = As + stg * 4096 + aoff;
        const char* Bb = Bs + stg * 8192 + boff;

        uint4 Ar[4];
        Ar[0] = *(const uint4*)(Ab);
        Ar[1] = *(const uint4*)(Ab + 512);
        Ar[2] = *(const uint4*)(Ab + 1024);
        Ar[3] = *(const uint4*)(Ab + 1536);
        #pragma unroll
        for (int half = 0; half < 2; half++) {
            uint4 Bv[4];
            #pragma unroll
            for (int j = 0; j < 4; j++)
                Bv[j] = *(const uint4*)(Bb + (half * 4 + j) * 512);
            #pragma unroll
            for (int s = 0; s < 2; s++)
                #pragma unroll
                for (int mf = 0; mf < 2; mf++) {
                    unsigned a0 = s ? Ar[2 * mf].z     : Ar[2 * mf].x;
                    unsigned a2 = s ? Ar[2 * mf].w     : Ar[2 * mf].y;
                    unsigned a1 = s ? Ar[2 * mf + 1].z : Ar[2 * mf + 1].x;
                    unsigned a3 = s ? Ar[2 * mf + 1].w : Ar[2 * mf + 1].y;
                    #pragma unroll
                    for (int j = 0; j < 4; j++)
                        mma16(c[mf][half * 4 + j], a0, a1, a2, a3,
                              s ? Bv[j].z : Bv[j].x, s ? Bv[j].w : Bv[j].y);
                }
        }
    }

    // epilogue: (optionally BN+ELU), fp16, permuted store
    size_t rowbase = (size_t)tile * 64;
    #pragma unroll
    for (int nf = 0; nf < 8; nf++) {
        int col = n0 + wn * 64 + nf * 8 + 2 * tig;
        int pcol = (col & ~31) + kperm(col & 31);
        float s0 = 1.f, s1 = 1.f, t0 = 0.f, t1 = 0.f;
        if (ACT) {
            s0 = __ldg(sc + col); s1 = __ldg(sc + col + 1);
            t0 = __ldg(sh + col); t1 = __ldg(sh + col + 1);
        }
        #pragma unroll
        for (int mf = 0; mf < 2; mf++) {
            int r = wm * 32 + mf * 16 + g;
            __half2 v01, v23;
            if (ACT) {
                v01 = __floats2half2_rn(eluf(s0 * c[mf][nf][0] + t0),
                                        eluf(s1 * c[mf][nf][1] + t1));
                v23 = __floats2half2_rn(eluf(s0 * c[mf][nf][2] + t0),
                                        eluf(s1 * c[mf][nf][3] + t1));
            } else {
                v01 = __floats2half2_rn(c[mf][nf][0], c[mf][nf][1]);
                v23 = __floats2half2_rn(c[mf][nf][2], c[mf][nf][3]);
            }
            *(__half2*)(outp + (rowbase + r) * NW + pcol)     = v01;
            *(__half2*)(outp + (rowbase + r + 8) * NW + pcol) = v23;
        }
    }
}

// ---------------- layer-1 single-shot GEMM: K=128, CTA 64x128, no ring ----------------
// Loads entire A tile (64x128 fp16 = 16KB) and B tile (4kc x 128n x 64B = 32KB)
// in one cp.async burst; ONE barrier; 128 MMAs straight. 4 CTAs/SM.
constexpr int SMEM_L1_B = 16384 + 32768;   // 48KB

__global__ void __launch_bounds__(128, 4)
l1_kernel(const __half* __restrict__ Ag,    // [NROWS][128] fp16 permuted
          const __half* __restrict__ W,     // [4][1024][32] fp16 permuted
          __half* __restrict__ outp)        // [NROWS][1024] fp16 permuted
{
    extern __shared__ char sm[];
    char* As = sm;                     // [64 rows][256B]
    char* Bs = sm + 16384;             // [4 kc][128 n][64B]

    const int tid  = threadIdx.x;
    const int tile = blockIdx.y;
    const int n0   = blockIdx.x * 128;

    const uint32_t sAb = (uint32_t)__cvta_generic_to_shared(As);
    const uint32_t sBb = (uint32_t)__cvta_generic_to_shared(Bs);
    const char* AgB = (const char*)Ag;
    const char* WB  = (const char*)W;

    // A: 16KB = 1024 x 16B slots. row = o>>4, seg = o&15.
    {
        int r = tid >> 4, seg = tid & 15;
        uint32_t d = sAb + (uint32_t)(r * 256 + seg * 16);
        const char* s = AgB + (size_t)(tile * 64 + r) * 256 + seg * 16;
        #pragma unroll
        for (int it = 0; it < 8; it++)          // rows advance by 8 per it
            cp16s(d + it * 2048, s + (size_t)it * 8 * 256);
    }
    // B: 32KB = 2048 x 16B slots. kc = o>>9, n = (o>>2)&127, seg = o&3.
    {
        int kc0 = tid >> 9;  (void)kc0;         // tid<128 -> kc from it
        int n = (tid >> 2) & 31, seg = tid & 3; // 128 thr cover 32 n-rows per it-step
        #pragma unroll
        for (int it = 0; it < 16; it++) {
            int o = tid + it * 128;
            int kc = o >> 9, nn = (o >> 2) & 127, sg = o & 3;
            cp16s(sBb + (uint32_t)(kc * 8192 + nn * 64 + sg * 16),
                  WB + (size_t)kc * 65536 + (size_t)(n0 + nn) * 64 + sg * 16);
        }
        (void)n; (void)seg;
    }
    cp_commit();
    cp_wait<0>();
    __syncthreads();

    const int wid = tid >> 5, lane = tid & 31;
    const int wm = wid >> 1, wn = wid & 1;            // 2x2 warp grid, warp 32x64
    const int g = lane >> 2, tig = lane & 3;
    const int aoff = (wm * 32 + g) * 256 + tig * 16;  // A row stride 256B
    const int boff = (wn * 64 + g) * 64 + tig * 16;

    float c[2][8][4];
    #pragma unroll
    for (int i = 0; i < 2; i++)
        #pragma unroll
        for (int j = 0; j < 8; j++)
            #pragma unroll
            for (int q = 0; q < 4; q++) c[i][j][q] = 0.f;

    #pragma unroll
    for (int kc = 0; kc < 4; kc++) {
        const char* Ab = As + aoff + kc * 64;
        const char* Bb = Bs + kc * 8192 + boff;

        uint4 Ar[4];
        Ar[0] = *(const uint4*)(Ab);              // row g
        Ar[1] = *(const uint4*)(Ab + 8 * 256);    // row g+8
        Ar[2] = *(const uint4*)(Ab + 16 * 256);   // row g+16
        Ar[3] = *(const uint4*)(Ab + 24 * 256);   // row g+24
        #pragma unroll
        for (int half = 0; half < 2; half++) {
            uint4 Bv[4];
            #pragma unroll
            for (int j = 0; j < 4; j++)
                Bv[j] = *(const uint4*)(Bb + (half * 4 + j) * 512);
            #pragma unroll
            for (int s = 0; s < 2; s++)
                #pragma unroll
                for (int mf = 0; mf < 2; mf++) {
                    unsigned a0 = s ? Ar[2 * mf].z     : Ar[2 * mf].x;
                    unsigned a2 = s ? Ar[2 * mf].w     : Ar[2 * mf].y;
                    unsigned a1 = s ? Ar[2 * mf + 1].z : Ar[2 * mf + 1].x;
                    unsigned a3 = s ? Ar[2 * mf + 1].w : Ar[2 * mf + 1].y;
                    #pragma unroll
                    for (int j = 0; j < 4; j++)
                        mma16(c[mf][half * 4 + j], a0, a1, a2, a3,
                              s ? Bv[j].z : Bv[j].x, s ? Bv[j].w : Bv[j].y);
                }
        }
    }

    // epilogue: raw fp16 permuted store into UV [NROWS][1024]
    size_t rowbase = (size_t)tile * 64;
    #pragma unroll
    for (int nf = 0; nf < 8; nf++) {
        int col = n0 + wn * 64 + nf * 8 + 2 * tig;
        int pcol = (col & ~31) + kperm(col & 31);
        #pragma unroll
        for (int mf = 0; mf < 2; mf++) {
            int r = wm * 32 + mf * 16 + g;
            __half2 v01 = __floats2half2_rn(c[mf][nf][0], c[mf][nf][1]);
            __half2 v23 = __floats2half2_rn(c[mf][nf][2], c[mf][nf][3]);
            *(__half2*)(outp + (rowbase + r) * 1024 + pcol)     = v01;
            *(__half2*)(outp + (rowbase + r + 8) * 1024 + pcol) = v23;
        }
    }
}

// ---------------- assemble: X1[e] = elu(scp*(U[e1]+V[e0])+shp), permuted fp16 ----------------
__global__ void __launch_bounds__(256, 4)
assemble_kernel(const __half* __restrict__ UV,
                const int* __restrict__ edges,
                const float* __restrict__ scp, const float* __restrict__ shp,
                __half* __restrict__ X1)
{
    const int lane = threadIdx.x & 31;
    const int wid  = threadIdx.x >> 5;
    const int eb   = blockIdx.x * 16 + wid;

    const uint4* pu[2];
    const uint4* pv[2];
    uint4* px[2];
    #pragma unroll
    for (int it = 0; it < 2; it++) {
        int e  = eb + it * 8;
        int e1 = __ldg(edges + NEDGES + e);
        int e0 = __ldg(edges + e);
        pu[it] = (const uint4*)(UV + (size_t)e1 * 1024);
        pv[it] = (const uint4*)(UV + (size_t)e0 * 1024 + 512);
        px[it] = (uint4*)(X1 + (size_t)e * 512);
    }

    #pragma unroll
    for (int j = 0; j < 2; j++) {
        const int idx = lane + j * 32;
        float4 sA = __ldg((const float4*)scp + idx * 2);
        float4 sB = __ldg((const float4*)scp + idx * 2 + 1);
        float4 tA = __ldg((const float4*)shp + idx * 2);
        float4 tB = __ldg((const float4*)shp + idx * 2 + 1);
        float sarr[8] = {sA.x, sA.y, sA.z, sA.w, sB.x, sB.y, sB.z, sB.w};
        float tarr[8] = {tA.x, tA.y, tA.z, tA.w, tB.x, tB.y, tB.z, tB.w};
        #pragma unroll
        for (int it = 0; it < 2; it++) {
            uint4 a = __ldg(pu[it] + idx);
            uint4 b = __ldg(pv[it] + idx);
            const __half2* ha = (const __half2*)&a;
            const __half2* hb = (const __half2*)&b;
            uint4 o;
            __half2* ho = (__half2*)&o;
            #pragma unroll
            for (int q = 0; q < 4; q++) {
                float2 fa = __half22float2(ha[q]);
                float2 fb = __half22float2(hb[q]);
                float x0 = eluf(sarr[2 * q]     * (fa.x + fb.x) + tarr[2 * q]);
                float x1 = eluf(sarr[2 * q + 1] * (fa.y + fb.y) + tarr[2 * q + 1]);
                ho[q] = __floats2half2_rn(x0, x1);
            }
            px[it][idx] = o;
        }
    }
}

// ---------------- head kernel (fp16) ----------------
constexpr int SMEM_HEAD_B = 32768 + 16384 + 128 * 33 * 4;   // 66,048 B (x3 = 198,144)

__global__ void __launch_bounds__(256, 3)
head_kernel(const __half* __restrict__ A,     // X fp16 permuted
            const __half* __restrict__ Wt,    // [16][32][32] fp16 permuted
            const float*  __restrict__ dist,
            float* __restrict__ out)
{
    extern __shared__ char hsm[];
    char*  Bp = hsm;
    char*  As = hsm + 32768;
    float* sZ = (float*)(hsm + 49152);

    const int tid  = threadIdx.x;
    const int tile = blockIdx.x;
    const char* AB = (const char*)A;

    #pragma unroll
    for (int it = 0; it < 8; it++) {
        int o = tid + it * 256;
        cp16(Bp + o * 16, (const char*)Wt + o * 16);
    }

    auto loadA = [&](int kc, int buf) {
        #pragma unroll
        for (int it = 0; it < 2; it++) {
            int o = tid + it * 256;
            int r = o >> 2, sg = o & 3;
            cp16(As + buf * 8192 + r * 64 + sg * 16,
                 AB + (size_t)(tile * 128 + r) * 1024 + kc * 64 + sg * 16);
        }
    };

    const int wid = tid >> 5, lane = tid & 31;
    const int g = lane >> 2, tig = lane & 3;
    const int aoff = (wid * 16 + g) * 64 + tig * 16;
    const int boff = g * 64 + tig * 16;

    float c[4][4];
    #pragma unroll
    for (int i = 0; i < 4; i++)
        #pragma unroll
        for (int q = 0; q < 4; q++) c[i][q] = 0.f;

    loadA(0, 0); cp_commit();

    #pragma unroll
    for (int kc = 0; kc < 16; kc++) {
        int buf = kc & 1;
        __syncthreads();
        if (kc + 1 < 16) { loadA(kc + 1, buf ^ 1); cp_commit(); cp_wait<1>(); }
        else             { cp_wait<0>(); }
        __syncthreads();

        const char* Ab = As + buf * 8192 + aoff;
        const char* Bb = Bp + kc * 2048 + boff;
        uint4 A0 = *(const uint4*)(Ab);
        uint4 A1 = *(const uint4*)(Ab + 512);
        uint4 Bv[4];
        #pragma unroll
        for (int j = 0; j < 4; j++)
            Bv[j] = *(const uint4*)(Bb + j * 512);
        #pragma unroll
        for (int s = 0; s < 2; s++) {
            unsigned a0 = s ? A0.z : A0.x;
            unsigned a2 = s ? A0.w : A0.y;
            unsigned a1 = s ? A1.z : A1.x;
            unsigned a3 = s ? A1.w : A1.y;
            #pragma unroll
            for (int j = 0; j < 4; j++)
                mma16(c[j], a0, a1, a2, a3,
                      s ? Bv[j].z : Bv[j].x, s ? Bv[j].w : Bv[j].y);
        }
    }

    {
        int r0 = wid * 16 + g;
        #pragma unroll
        for (int nf = 0; nf < 4; nf++) {
            int co = nf * 8 + 2 * tig;
            sZ[r0 * 33 + co]           = c[nf][0];
            sZ[r0 * 33 + co + 1]       = c[nf][1];
            sZ[(r0 + 8) * 33 + co]     = c[nf][2];
            sZ[(r0 + 8) * 33 + co + 1] = c[nf][3];
        }
    }
    __syncthreads();

    if (tid < 128) {
        int e = tile * 128 + tid;
        if (e < NEDGES) {
            float z[30];
            #pragma unroll
            for (int k = 0; k < 30; k++) z[k] = sZ[tid * 33 + k] + g_hb[k];
            float m = z[0];
            #pragma unroll
            for (int k = 1; k < 10; k++) m = fmaxf(m, z[k]);
            float ez[10], sum = 0.f;
            #pragma unroll
            for (int k = 0; k < 10; k++) { ez[k] = __expf(z[k] - m); sum += ez[k]; }
            float inv = 1.f / sum;
            #pragma unroll
            for (int k = 0; k < 10; k++) out[(size_t)e * 10 + k] = ez[k] * inv;
            #pragma unroll
            for (int k = 0; k < 10; k++)
                out[5000000u + (size_t)e * 10 + k] = eluf(z[10 + k]) + 1.1f;
            #pragma unroll
            for (int k = 0; k < 10; k++)
                out[10000000u + (size_t)e * 10 + k] = eluf(z[20 + k]) + 1.0f;
            out[15000000u + e] = __ldg(dist + e);
        }
    }
}

// ---------------- launch ----------------
extern "C" void kernel_launch(void* const* d_in, const int* in_sizes, int n_in,
                              void* d_out, int out_size) {
    (void)in_sizes; (void)n_in; (void)out_size;
    const float* h    = (const float*)d_in[0];
    const int*   edges= (const int*)  d_in[1];
    const float* dist = (const float*)d_in[2];
    const float* W0   = (const float*)d_in[3];
    const float* b0   = (const float*)d_in[4];
    const float* Wh   = (const float*)d_in[5];
    const float* bh   = (const float*)d_in[6];
    const float* gm   = (const float*)d_in[7];
    const float* bt   = (const float*)d_in[8];
    const float* mn   = (const float*)d_in[9];
    const float* vr   = (const float*)d_in[10];
    const float* Wpi  = (const float*)d_in[11];
    const float* bpi  = (const float*)d_in[12];
    const float* Wsg  = (const float*)d_in[13];
    const float* bsg  = (const float*)d_in[14];
    const float* Wmu  = (const float*)d_in[15];
    const float* bmu  = (const float*)d_in[16];
    float* out = (float*)d_out;

    cudaFuncSetAttribute(l1_kernel,                   cudaFuncAttributeMaxDynamicSharedMemorySize, SMEM_L1_B);
    cudaFuncSetAttribute(gemm_kernel<512, 512, true>, cudaFuncAttributeMaxDynamicSharedMemorySize, SMEM_MAIN_B);
    cudaFuncSetAttribute(head_kernel,                 cudaFuncAttributeMaxDynamicSharedMemorySize, SMEM_HEAD_B);

    __half *hp, *X1, *X2, *W0m, *Whh, *WHh;
    float *sc, *sh, *scp, *shp;
    cudaGetSymbolAddress((void**)&hp,  g_hp);
    cudaGetSymbolAddress((void**)&X1,  g_X1);
    cudaGetSymbolAddress((void**)&X2,  g_X2);
    cudaGetSymbolAddress((void**)&W0m, g_W0m);
    cudaGetSymbolAddress((void**)&Whh, g_Whh);
    cudaGetSymbolAddress((void**)&WHh, g_WHh);
    cudaGetSymbolAddress((void**)&sc,  g_sc);
    cudaGetSymbolAddress((void**)&sh,  g_sh);
    cudaGetSymbolAddress((void**)&scp, g_scp);
    cudaGetSymbolAddress((void**)&shp, g_shp);

    __half* UV = X2;                                  // [NROWS][1024]

    prep_kernel<<<512, 256>>>(h, W0, b0, Wh, bh, gm, bt, mn, vr,
                              Wpi, bpi, Wsg, bsg, Wmu, bmu);

    // layer 1 at node level (merged, single-shot K=128): UV = hp @ [W0top | W0bot]
    dim3 gridN(8, TILESN);
    l1_kernel<<<gridN, 128, SMEM_L1_B>>>(hp, W0m, UV);
    // edge assembly + BN + ELU -> X1
    assemble_kernel<<<NEDGES / 16, 256>>>(UV, edges, scp, shp, X1);

    // hidden layers
    dim3 gridE(4, TILES64);
    gemm_kernel<512, 512, true><<<gridE, 128, SMEM_MAIN_B>>>(X1, Whh,                 sc + 512,  sh + 512,  X2);
    gemm_kernel<512, 512, true><<<gridE, 128, SMEM_MAIN_B>>>(X2, Whh + 16 * 512 * 32, sc + 1024, sh + 1024, X1);

    head_kernel<<<TILESH, 256, SMEM_HEAD_B>>>(X1, WHh, dist, out);
}

// round 17
// speedup vs baseline: 1.5026x; 1.5026x over previous
#include <cuda_runtime.h>
#include <cuda_fp16.h>
#include <cstdint>
#include <cstddef>

#define NEDGES 500000
#define NNODES 200000

constexpr int MROWS   = 500096;            // mult of 128
constexpr int TILES64 = MROWS / 64;        // 7814 (edge-row tiles)
constexpr int TILESN  = NNODES / 64;       // 3125 (node-row tiles)
constexpr int TILESH  = MROWS / 128;       // 3907

// ---------------- device scratch ----------------
__device__ __half g_hp[(size_t)NNODES * 128];       // h fp16, k-permuted per 32-chunk
__device__ __half g_X1[(size_t)MROWS * 512];        // activations fp16, k-permuted
__device__ __half g_X2[(size_t)MROWS * 512];        // also hosts UV [NNODES][1024]
__device__ __half g_W0m[4 * 1024 * 32];             // merged W0 [kc][n(U|V)][kp]
__device__ __half g_Whh[2 * 16 * 512 * 32];         // hidden W [l][kc][n][kp]
__device__ __half g_WHh[16 * 32 * 32];              // head W [kc][n][kp]
__device__ float  g_sc[3 * 512];
__device__ float  g_sh[3 * 512];
__device__ float  g_scp[512];                       // layer-0 BN scale, permuted
__device__ float  g_shp[512];                       // layer-0 BN shift, permuted
__device__ float  g_hb[32];

// k-permutation within a 32-k chunk: lane tig gets its 8 fragment halves contiguous.
__host__ __device__ __forceinline__ int kperm(int k) {
    return ((k & 7) >> 1) * 8 + ((k >> 4) & 1) * 4 + ((k >> 3) & 1) * 2 + (k & 1);
}

// ---------------- helpers ----------------
__device__ __forceinline__ void cp16s(uint32_t s, const void* g) {
    asm volatile("cp.async.cg.shared.global [%0], [%1], 16;\n" :: "r"(s), "l"(g));
}
__device__ __forceinline__ void cp16(void* s, const void* g) {
    unsigned ss = (unsigned)__cvta_generic_to_shared(s);
    asm volatile("cp.async.cg.shared.global [%0], [%1], 16;\n" :: "r"(ss), "l"(g));
}
__device__ __forceinline__ void cp_commit() { asm volatile("cp.async.commit_group;\n"); }
template<int N> __device__ __forceinline__ void cp_wait() {
    asm volatile("cp.async.wait_group %0;\n" :: "n"(N) : "memory");
}
__device__ __forceinline__ void mma16(float* c,
                                      unsigned a0, unsigned a1, unsigned a2, unsigned a3,
                                      unsigned b0, unsigned b1) {
    asm volatile(
        "mma.sync.aligned.m16n8k16.row.col.f32.f16.f16.f32 "
        "{%0,%1,%2,%3},{%4,%5,%6,%7},{%8,%9},{%0,%1,%2,%3};"
        : "+f"(c[0]), "+f"(c[1]), "+f"(c[2]), "+f"(c[3])
        : "r"(a0), "r"(a1), "r"(a2), "r"(a3), "r"(b0), "r"(b1));
}
// fast ELU: __expf = MUFU.EX2 path (~2 instr), abs err ~1e-6 — far inside tolerance
__device__ __forceinline__ float eluf(float v) { return v > 0.f ? v : (__expf(v) - 1.f); }

// ---------------- prep: convert everything to permuted fp16, fold BN ----------------
__global__ void prep_kernel(
    const float* __restrict__ h,
    const float* __restrict__ W0,  const float* __restrict__ b0,
    const float* __restrict__ Wh,  const float* __restrict__ bh,
    const float* __restrict__ gm,  const float* __restrict__ bt,
    const float* __restrict__ mn,  const float* __restrict__ vr,
    const float* __restrict__ Wpi, const float* __restrict__ bpi,
    const float* __restrict__ Wsg, const float* __restrict__ bsg,
    const float* __restrict__ Wmu, const float* __restrict__ bmu)
{
    int st = gridDim.x * blockDim.x;
    int t0 = blockIdx.x * blockDim.x + threadIdx.x;
    for (int o = t0; o < NNODES * 128; o += st) {
        int node = o >> 7, kk = o & 127;
        int ch = kk >> 5, k = kk & 31;
        g_hp[(size_t)node * 128 + ch * 32 + kperm(k)] = __float2half(h[o]);
    }
    // merged W0: cols 0..511 = top half (k 0..127 -> h[edge1]) -> U,
    //            cols 512..1023 = bottom (k 128..255 -> h[edge0]) -> V
    for (int o = t0; o < 4 * 1024 * 32; o += st) {
        int kc = o >> 15, n = (o >> 5) & 1023, k = o & 31;
        float v = (n < 512) ? W0[(size_t)(kc * 32 + k) * 512 + n]
                            : W0[(size_t)(kc * 32 + k + 128) * 512 + (n - 512)];
        g_W0m[(size_t)kc * 32768 + n * 32 + kperm(k)] = __float2half(v);
    }
    for (int o = t0; o < 2 * 16 * 512 * 32; o += st) {
        int l = o >> 18;
        int kc = (o >> 14) & 15, n = (o >> 5) & 511, k = o & 31;
        g_Whh[(size_t)l * 262144 + (size_t)kc * 16384 + n * 32 + kperm(k)] =
            __float2half(Wh[(size_t)l * 262144 + (size_t)(kc * 32 + k) * 512 + n]);
    }
    for (int o = t0; o < 16 * 32 * 32; o += st) {
        int kc = o >> 10, n = (o >> 5) & 31, k = o & 31;
        int kk = kc * 32 + k;
        float v = (n < 10) ? Wpi[kk * 10 + n]
                : (n < 20) ? Wsg[kk * 10 + (n - 10)]
                : (n < 30) ? Wmu[kk * 10 + (n - 20)] : 0.f;
        g_WHh[kc * 1024 + n * 32 + kperm(k)] = __float2half(v);
    }
    for (int i = t0; i < 3 * 512; i += st) {
        int l = i >> 9, c = i & 511;
        float s = gm[i] * rsqrtf(vr[i] + 1e-5f);
        float bb = (l == 0) ? b0[c] : bh[(l - 1) * 512 + c];
        g_sc[i] = s;
        g_sh[i] = (bb - mn[i]) * s + bt[i];
        if (l == 0) {
            int pi = (c & ~31) + kperm(c & 31);
            g_scp[pi] = s;
            g_shp[pi] = (bb - mn[i]) * s + bt[i];
        }
    }
    for (int i = t0; i < 32; i += st)
        g_hb[i] = (i < 10) ? bpi[i] : (i < 20) ? bsg[i - 10] : (i < 30) ? bmu[i - 20] : 0.f;
}

// ---------------- main GEMM (fp16, fully unrolled K loop) ----------------
// CTA tile M=64 x N=128, 128 threads (4 warps, warp 32x64), 4 CTAs/SM.
// K chunk 32, 4-stage ring, prefetch distance 3, 1 barrier/chunk.
// NW = weight N-dim = output row stride (512 hidden, 1024 merged layer-1).
constexpr int SMEM_MAIN_B = 16384 + 32768;   // 49,152 (x4 CTAs = 196,608)

template<int KDIM, int NW, bool ACT>
__global__ void __launch_bounds__(128, 4)
gemm_kernel(const __half* __restrict__ Ag,    // [rows][KDIM] fp16 permuted
            const __half* __restrict__ W,     // [KDIM/32][NW][32] fp16 permuted
            const float*  __restrict__ sc,
            const float*  __restrict__ sh,
            __half* __restrict__ outp)        // [rows][NW] fp16 permuted
{
    extern __shared__ char sm[];
    char* As = sm;                     // 4 * 4096 B
    char* Bs = sm + 16384;             // 4 * 8192 B

    const int tid  = threadIdx.x;
    const int tile = blockIdx.y;
    const int n0   = blockIdx.x * 128;
    constexpr int NC = KDIM / 32;

    const int seg = tid & 3;               // 16B segment in 64B row
    const int r0  = tid >> 2;              // 0..31
    const uint32_t sAb = (uint32_t)__cvta_generic_to_shared(As);
    const uint32_t sBb = (uint32_t)__cvta_generic_to_shared(Bs);
    const uint32_t dA0 = sAb + (uint32_t)(r0 * 64 + seg * 16);
    const uint32_t dB0 = sBb + (uint32_t)(r0 * 64 + seg * 16);
    const char* AgB = (const char*)Ag;
    const char* WB  = (const char*)W;
    const char* srcA0 = AgB + (size_t)(tile * 64 + r0) * (KDIM * 2) + seg * 16;
    const char* srcB0 = WB + (size_t)(n0 + r0) * 64 + seg * 16;

    auto prefetch = [&](int kc) {
        const int stg = kc & 3;
        const uint32_t soA = (uint32_t)stg * 4096;
        const uint32_t soB = (uint32_t)stg * 8192;
        const char* s = srcA0 + kc * 64;
        #pragma unroll
        for (int it = 0; it < 2; it++)
            cp16s(dA0 + soA + it * 2048, s + (size_t)it * 32 * (KDIM * 2));
        const char* sb = srcB0 + (size_t)kc * (NW * 64);
        #pragma unroll
        for (int it = 0; it < 4; it++)
            cp16s(dB0 + soB + it * 2048, sb + (size_t)it * 2048);
        cp_commit();
    };

    const int wid = tid >> 5, lane = tid & 31;
    const int wm = wid >> 1, wn = wid & 1;            // 2x2 warp grid
    const int g = lane >> 2, tig = lane & 3;
    const int aoff = (wm * 32 + g) * 64 + tig * 16;
    const int boff = (wn * 64 + g) * 64 + tig * 16;

    float c[2][8][4];
    #pragma unroll
    for (int i = 0; i < 2; i++)
        #pragma unroll
        for (int j = 0; j < 8; j++)
            #pragma unroll
            for (int q = 0; q < 4; q++) c[i][j][q] = 0.f;

    prefetch(0);
    prefetch(1);
    prefetch(2);

    #pragma unroll
    for (int kc = 0; kc < NC; kc++) {
        if (kc + 3 < NC) cp_wait<2>();
        else if (kc + 2 < NC) cp_wait<1>();
        else cp_wait<0>();
        __syncthreads();
        if (kc + 3 < NC) prefetch(kc + 3);

        const int stg = kc & 3;
        const char* Ab = As + stg * 4096 + aoff;
        const char* Bb = Bs + stg * 8192 + boff;

        uint4 Ar[4];
        Ar[0] = *(const uint4*)(Ab);
        Ar[1] = *(const uint4*)(Ab + 512);
        Ar[2] = *(const uint4*)(Ab + 1024);
        Ar[3] = *(const uint4*)(Ab + 1536);
        #pragma unroll
        for (int half = 0; half < 2; half++) {
            uint4 Bv[4];
            #pragma unroll
            for (int j = 0; j < 4; j++)
                Bv[j] = *(const uint4*)(Bb + (half * 4 + j) * 512);
            #pragma unroll
            for (int s = 0; s < 2; s++)
                #pragma unroll
                for (int mf = 0; mf < 2; mf++) {
                    unsigned a0 = s ? Ar[2 * mf].z     : Ar[2 * mf].x;
                    unsigned a2 = s ? Ar[2 * mf].w     : Ar[2 * mf].y;
                    unsigned a1 = s ? Ar[2 * mf + 1].z : Ar[2 * mf + 1].x;
                    unsigned a3 = s ? Ar[2 * mf + 1].w : Ar[2 * mf + 1].y;
                    #pragma unroll
                    for (int j = 0; j < 4; j++)
                        mma16(c[mf][half * 4 + j], a0, a1, a2, a3,
                              s ? Bv[j].z : Bv[j].x, s ? Bv[j].w : Bv[j].y);
                }
        }
    }

    // epilogue: (optionally BN+ELU), fp16, permuted store
    size_t rowbase = (size_t)tile * 64;
    #pragma unroll
    for (int nf = 0; nf < 8; nf++) {
        int col = n0 + wn * 64 + nf * 8 + 2 * tig;
        int pcol = (col & ~31) + kperm(col & 31);
        float s0 = 1.f, s1 = 1.f, t0 = 0.f, t1 = 0.f;
        if (ACT) {
            s0 = __ldg(sc + col); s1 = __ldg(sc + col + 1);
            t0 = __ldg(sh + col); t1 = __ldg(sh + col + 1);
        }
        #pragma unroll
        for (int mf = 0; mf < 2; mf++) {
            int r = wm * 32 + mf * 16 + g;
            __half2 v01, v23;
            if (ACT) {
                v01 = __floats2half2_rn(eluf(s0 * c[mf][nf][0] + t0),
                                        eluf(s1 * c[mf][nf][1] + t1));
                v23 = __floats2half2_rn(eluf(s0 * c[mf][nf][2] + t0),
                                        eluf(s1 * c[mf][nf][3] + t1));
            } else {
                v01 = __floats2half2_rn(c[mf][nf][0], c[mf][nf][1]);
                v23 = __floats2half2_rn(c[mf][nf][2], c[mf][nf][3]);
            }
            *(__half2*)(outp + (rowbase + r) * NW + pcol)     = v01;
            *(__half2*)(outp + (rowbase + r + 8) * NW + pcol) = v23;
        }
    }
}

// ---------------- assemble: X1[e] = elu(scp*(U[e1]+V[e0])+shp), permuted fp16 ----------------
__global__ void __launch_bounds__(256, 4)
assemble_kernel(const __half* __restrict__ UV,
                const int* __restrict__ edges,
                const float* __restrict__ scp, const float* __restrict__ shp,
                __half* __restrict__ X1)
{
    const int lane = threadIdx.x & 31;
    const int wid  = threadIdx.x >> 5;
    const int eb   = blockIdx.x * 16 + wid;

    const uint4* pu[2];
    const uint4* pv[2];
    uint4* px[2];
    #pragma unroll
    for (int it = 0; it < 2; it++) {
        int e  = eb + it * 8;
        int e1 = __ldg(edges + NEDGES + e);
        int e0 = __ldg(edges + e);
        pu[it] = (const uint4*)(UV + (size_t)e1 * 1024);
        pv[it] = (const uint4*)(UV + (size_t)e0 * 1024 + 512);
        px[it] = (uint4*)(X1 + (size_t)e * 512);
    }

    #pragma unroll
    for (int j = 0; j < 2; j++) {
        const int idx = lane + j * 32;
        float4 sA = __ldg((const float4*)scp + idx * 2);
        float4 sB = __ldg((const float4*)scp + idx * 2 + 1);
        float4 tA = __ldg((const float4*)shp + idx * 2);
        float4 tB = __ldg((const float4*)shp + idx * 2 + 1);
        float sarr[8] = {sA.x, sA.y, sA.z, sA.w, sB.x, sB.y, sB.z, sB.w};
        float tarr[8] = {tA.x, tA.y, tA.z, tA.w, tB.x, tB.y, tB.z, tB.w};
        #pragma unroll
        for (int it = 0; it < 2; it++) {
            uint4 a = __ldg(pu[it] + idx);
            uint4 b = __ldg(pv[it] + idx);
            const __half2* ha = (const __half2*)&a;
            const __half2* hb = (const __half2*)&b;
            uint4 o;
            __half2* ho = (__half2*)&o;
            #pragma unroll
            for (int q = 0; q < 4; q++) {
                float2 fa = __half22float2(ha[q]);
                float2 fb = __half22float2(hb[q]);
                float x0 = eluf(sarr[2 * q]     * (fa.x + fb.x) + tarr[2 * q]);
                float x1 = eluf(sarr[2 * q + 1] * (fa.y + fb.y) + tarr[2 * q + 1]);
                ho[q] = __floats2half2_rn(x0, x1);
            }
            px[it][idx] = o;
        }
    }
}

// ---------------- head kernel (fp16) ----------------
constexpr int SMEM_HEAD_B = 32768 + 16384 + 128 * 33 * 4;   // 66,048 B (x3 = 198,144)

__global__ void __launch_bounds__(256, 3)
head_kernel(const __half* __restrict__ A,     // X fp16 permuted
            const __half* __restrict__ Wt,    // [16][32][32] fp16 permuted
            const float*  __restrict__ dist,
            float* __restrict__ out)
{
    extern __shared__ char hsm[];
    char*  Bp = hsm;
    char*  As = hsm + 32768;
    float* sZ = (float*)(hsm + 49152);

    const int tid  = threadIdx.x;
    const int tile = blockIdx.x;
    const char* AB = (const char*)A;

    #pragma unroll
    for (int it = 0; it < 8; it++) {
        int o = tid + it * 256;
        cp16(Bp + o * 16, (const char*)Wt + o * 16);
    }

    auto loadA = [&](int kc, int buf) {
        #pragma unroll
        for (int it = 0; it < 2; it++) {
            int o = tid + it * 256;
            int r = o >> 2, sg = o & 3;
            cp16(As + buf * 8192 + r * 64 + sg * 16,
                 AB + (size_t)(tile * 128 + r) * 1024 + kc * 64 + sg * 16);
        }
    };

    const int wid = tid >> 5, lane = tid & 31;
    const int g = lane >> 2, tig = lane & 3;
    const int aoff = (wid * 16 + g) * 64 + tig * 16;
    const int boff = g * 64 + tig * 16;

    float c[4][4];
    #pragma unroll
    for (int i = 0; i < 4; i++)
        #pragma unroll
        for (int q = 0; q < 4; q++) c[i][q] = 0.f;

    loadA(0, 0); cp_commit();

    #pragma unroll
    for (int kc = 0; kc < 16; kc++) {
        int buf = kc & 1;
        __syncthreads();
        if (kc + 1 < 16) { loadA(kc + 1, buf ^ 1); cp_commit(); cp_wait<1>(); }
        else             { cp_wait<0>(); }
        __syncthreads();

        const char* Ab = As + buf * 8192 + aoff;
        const char* Bb = Bp + kc * 2048 + boff;
        uint4 A0 = *(const uint4*)(Ab);
        uint4 A1 = *(const uint4*)(Ab + 512);
        uint4 Bv[4];
        #pragma unroll
        for (int j = 0; j < 4; j++)
            Bv[j] = *(const uint4*)(Bb + j * 512);
        #pragma unroll
        for (int s = 0; s < 2; s++) {
            unsigned a0 = s ? A0.z : A0.x;
            unsigned a2 = s ? A0.w : A0.y;
            unsigned a1 = s ? A1.z : A1.x;
            unsigned a3 = s ? A1.w : A1.y;
            #pragma unroll
            for (int j = 0; j < 4; j++)
                mma16(c[j], a0, a1, a2, a3,
                      s ? Bv[j].z : Bv[j].x, s ? Bv[j].w : Bv[j].y);
        }
    }

    {
        int r0 = wid * 16 + g;
        #pragma unroll
        for (int nf = 0; nf < 4; nf++) {
            int co = nf * 8 + 2 * tig;
            sZ[r0 * 33 + co]           = c[nf][0];
            sZ[r0 * 33 + co + 1]       = c[nf][1];
            sZ[(r0 + 8) * 33 + co]     = c[nf][2];
            sZ[(r0 + 8) * 33 + co + 1] = c[nf][3];
        }
    }
    __syncthreads();

    if (tid < 128) {
        int e = tile * 128 + tid;
        if (e < NEDGES) {
            float z[30];
            #pragma unroll
            for (int k = 0; k < 30; k++) z[k] = sZ[tid * 33 + k] + g_hb[k];
            float m = z[0];
            #pragma unroll
            for (int k = 1; k < 10; k++) m = fmaxf(m, z[k]);
            float ez[10], sum = 0.f;
            #pragma unroll
            for (int k = 0; k < 10; k++) { ez[k] = __expf(z[k] - m); sum += ez[k]; }
            float inv = 1.f / sum;
            #pragma unroll
            for (int k = 0; k < 10; k++) out[(size_t)e * 10 + k] = ez[k] * inv;
            #pragma unroll
            for (int k = 0; k < 10; k++)
                out[5000000u + (size_t)e * 10 + k] = eluf(z[10 + k]) + 1.1f;
            #pragma unroll
            for (int k = 0; k < 10; k++)
                out[10000000u + (size_t)e * 10 + k] = eluf(z[20 + k]) + 1.0f;
            out[15000000u + e] = __ldg(dist + e);
        }
    }
}

// ---------------- launch ----------------
extern "C" void kernel_launch(void* const* d_in, const int* in_sizes, int n_in,
                              void* d_out, int out_size) {
    (void)in_sizes; (void)n_in; (void)out_size;
    const float* h    = (const float*)d_in[0];
    const int*   edges= (const int*)  d_in[1];
    const float* dist = (const float*)d_in[2];
    const float* W0   = (const float*)d_in[3];
    const float* b0   = (const float*)d_in[4];
    const float* Wh   = (const float*)d_in[5];
    const float* bh   = (const float*)d_in[6];
    const float* gm   = (const float*)d_in[7];
    const float* bt   = (const float*)d_in[8];
    const float* mn   = (const float*)d_in[9];
    const float* vr   = (const float*)d_in[10];
    const float* Wpi  = (const float*)d_in[11];
    const float* bpi  = (const float*)d_in[12];
    const float* Wsg  = (const float*)d_in[13];
    const float* bsg  = (const float*)d_in[14];
    const float* Wmu  = (const float*)d_in[15];
    const float* bmu  = (const float*)d_in[16];
    float* out = (float*)d_out;

    cudaFuncSetAttribute(gemm_kernel<128, 1024, false>, cudaFuncAttributeMaxDynamicSharedMemorySize, SMEM_MAIN_B);
    cudaFuncSetAttribute(gemm_kernel<512, 512, true>,   cudaFuncAttributeMaxDynamicSharedMemorySize, SMEM_MAIN_B);
    cudaFuncSetAttribute(head_kernel,                   cudaFuncAttributeMaxDynamicSharedMemorySize, SMEM_HEAD_B);

    __half *hp, *X1, *X2, *W0m, *Whh, *WHh;
    float *sc, *sh, *scp, *shp;
    cudaGetSymbolAddress((void**)&hp,  g_hp);
    cudaGetSymbolAddress((void**)&X1,  g_X1);
    cudaGetSymbolAddress((void**)&X2,  g_X2);
    cudaGetSymbolAddress((void**)&W0m, g_W0m);
    cudaGetSymbolAddress((void**)&Whh, g_Whh);
    cudaGetSymbolAddress((void**)&WHh, g_WHh);
    cudaGetSymbolAddress((void**)&sc,  g_sc);
    cudaGetSymbolAddress((void**)&sh,  g_sh);
    cudaGetSymbolAddress((void**)&scp, g_scp);
    cudaGetSymbolAddress((void**)&shp, g_shp);

    __half* UV = X2;                                  // [NNODES][1024]

    prep_kernel<<<1024, 256>>>(h, W0, b0, Wh, bh, gm, bt, mn, vr,
                               Wpi, bpi, Wsg, bsg, Wmu, bmu);

    // layer 1 at node level (merged): UV = hp @ [W0top | W0bot]
    dim3 gridN(8, TILESN);
    gemm_kernel<128, 1024, false><<<gridN, 128, SMEM_MAIN_B>>>(hp, W0m, sc, sh, UV);
    // edge assembly + BN + ELU -> X1
    assemble_kernel<<<NEDGES / 16, 256>>>(UV, edges, scp, shp, X1);

    // hidden layers
    dim3 gridE(4, TILES64);
    gemm_kernel<512, 512, true><<<gridE, 128, SMEM_MAIN_B>>>(X1, Whh,                 sc + 512,  sh + 512,  X2);
    gemm_kernel<512, 512, true><<<gridE, 128, SMEM_MAIN_B>>>(X2, Whh + 16 * 512 * 32, sc + 1024, sh + 1024, X1);

    head_kernel<<<TILESH, 256, SMEM_HEAD_B>>>(X1, WHh, dist, out);
}